// round 10
// baseline (speedup 1.0000x reference)
#include <cuda_runtime.h>
#include <cuda_bf16.h>
#include <cstdint>

// ---------------- problem constants ----------------
#define BB      4
#define TT      128
#define THIST   120
#define NSTEPS  8
#define DM      512
#define NH      8
#define DH      64
#define DFF     2048
#define DIN     32
#define NL      4
#define NSUB    5

#define SCALE_EMB 22.627416997969522f   // sqrt(512)
#define NEG_INF  (-3.402823466e38f)
#define LN10000  9.210340371976184f

// ---------------- device scratch (static, no allocation) ----------------
__device__ float g_buf [BB*TT*DIN];
__device__ float g_h   [BB*TT*DM];
__device__ float g_q   [BB*TT*DM];
__device__ float g_k   [BB*TT*DM];
__device__ float g_v   [BB*TT*DM];
__device__ float g_attn[BB*TT*DM];
__device__ float g_ff  [BB*TT*DFF];
__device__ float g_part[4*BB*TT*DM];    // split-K partials (wo uses 2, w2 uses 4)
__device__ float g_wfused [DFF*DIN];
__device__ float g_ctxterm[BB*DFF];

// ---------------- PDL intrinsics ----------------
// wait: block until all dependency grids fully complete (incl. memory flush).
// launch_dependents: allow dependent grids to be scheduled early; they still
// block in their own wait. Correctness-neutral, pure overlap.
__device__ __forceinline__ void gdc_wait() {
    asm volatile("griddepcontrol.wait;" ::: "memory");
}
__device__ __forceinline__ void gdc_ld() {
    asm volatile("griddepcontrol.launch_dependents;" ::: "memory");
}
#define GDC() do { gdc_wait(); gdc_ld(); } while (0)

// ---------------- helpers ----------------
__device__ __forceinline__ float gelu_tanh(float x) {
    float x3 = x * x * x;
    float t  = tanhf(0.7978845608028654f * (x + 0.044715f * x3));
    return 0.5f * x * (1.0f + t);
}

__device__ __forceinline__ uint32_t f2tf32(float x) {
    uint32_t r;
    asm("cvt.rna.tf32.f32 %0, %1;" : "=r"(r) : "f"(x));
    return r;
}

__device__ __forceinline__ void mma_tf32(float c[4],
    uint32_t a0, uint32_t a1, uint32_t a2, uint32_t a3,
    uint32_t b0, uint32_t b1)
{
    asm volatile(
        "mma.sync.aligned.m16n8k8.row.col.f32.tf32.tf32.f32 "
        "{%0,%1,%2,%3}, {%4,%5,%6,%7}, {%8,%9}, {%0,%1,%2,%3};"
        : "+f"(c[0]), "+f"(c[1]), "+f"(c[2]), "+f"(c[3])
        : "r"(a0), "r"(a1), "r"(a2), "r"(a3), "r"(b0), "r"(b1));
}

// ---------------- init: buf = [history ; zeros] ----------------
__global__ void init_kernel(const float* __restrict__ hist) {
    GDC();
    int idx = blockIdx.x * 256 + threadIdx.x;
    if (idx >= BB*TT*DIN) return;
    int b = idx >> 12;
    int t = (idx >> 5) & 127;
    int k = idx & 31;
    g_buf[idx] = (t < THIST) ? hist[(b*THIST + t)*DIN + k] : 0.0f;
}

// ---------------- precompute Wfused = scale * Wr1[:, :512] @ W_emb ----------------
__global__ void wfused_kernel(const float* __restrict__ Wr1, const float* __restrict__ Wemb) {
    GDC();
    int idx = blockIdx.x * 256 + threadIdx.x;
    int i = idx >> 5;
    int m = idx & 31;
    const float* w = Wr1 + (size_t)i * (2*DM);
    float s = 0.0f;
    #pragma unroll 8
    for (int j = 0; j < DM; j++) s += w[j] * Wemb[j*DIN + m];
    g_wfused[i*DIN + m] = s * SCALE_EMB;
}

// ---------------- embedding + positional encoding ----------------
__global__ void embed_kernel(const float* __restrict__ Wemb, const float* __restrict__ bemb) {
    GDC();
    int bt = blockIdx.x;                 // 0..511
    int t  = bt & 127;
    __shared__ float row[DIN];
    if (threadIdx.x < DIN) row[threadIdx.x] = g_buf[bt*DIN + threadIdx.x];
    __syncthreads();
    for (int d = threadIdx.x; d < DM; d += blockDim.x) {
        float s = bemb[d];
        const float* w = Wemb + d*DIN;
        #pragma unroll
        for (int k = 0; k < DIN; k++) s += row[k] * w[k];
        int i = d >> 1;
        float div = expf((float)(2*i) * (-LN10000 / (float)DM));
        float ang = (float)t * div;
        float pe  = (d & 1) ? cosf(ang) : sinf(ang);
        g_h[bt*DM + d] = s * SCALE_EMB + pe;
    }
}

// ================= tf32 tensor-core tile body (256 threads) =================
// tile 64x64, K chunk 32; 8 warps 2x4, warp does 32x16. Smem stride 36.
#define SM_STRIDE 36

__device__ __forceinline__ void gemm_tc_body(
    const float* __restrict__ A, const float* __restrict__ W,
    int lda, int ldw, int kbeg, int klen,
    int m0, int n0, float acc[2][2][4],
    uint32_t (*As)[SM_STRIDE], uint32_t (*Bs)[SM_STRIDE])
{
    int tid  = threadIdx.x;
    int lane = tid & 31;
    int wrp  = tid >> 5;
    int wm0 = (wrp >> 2) * 32;
    int wn0 = (wrp & 3) * 16;

    int lrow = tid >> 3;          // 0..31
    int lcol = (tid & 7) * 4;     // 0..28

    const float* Ab  = A + (size_t)(m0 + lrow) * lda + kbeg + lcol;
    const float* Ab2 = Ab + (size_t)32 * lda;
    const float* Wb  = W + (size_t)(n0 + lrow) * ldw + kbeg + lcol;
    const float* Wb2 = Wb + (size_t)32 * ldw;

    float4 pa0 = *(const float4*)(Ab);
    float4 pa1 = *(const float4*)(Ab2);
    float4 pb0 = *(const float4*)(Wb);
    float4 pb1 = *(const float4*)(Wb2);

    for (int kc = 0; kc < klen; kc += 32) {
        __syncthreads();
        {
            uint4 u;
            u.x=f2tf32(pa0.x); u.y=f2tf32(pa0.y); u.z=f2tf32(pa0.z); u.w=f2tf32(pa0.w);
            *(uint4*)&As[lrow][lcol] = u;
            u.x=f2tf32(pa1.x); u.y=f2tf32(pa1.y); u.z=f2tf32(pa1.z); u.w=f2tf32(pa1.w);
            *(uint4*)&As[lrow+32][lcol] = u;
            u.x=f2tf32(pb0.x); u.y=f2tf32(pb0.y); u.z=f2tf32(pb0.z); u.w=f2tf32(pb0.w);
            *(uint4*)&Bs[lrow][lcol] = u;
            u.x=f2tf32(pb1.x); u.y=f2tf32(pb1.y); u.z=f2tf32(pb1.z); u.w=f2tf32(pb1.w);
            *(uint4*)&Bs[lrow+32][lcol] = u;
        }
        __syncthreads();

        if (kc + 32 < klen) {
            pa0 = *(const float4*)(Ab  + kc + 32);
            pa1 = *(const float4*)(Ab2 + kc + 32);
            pb0 = *(const float4*)(Wb  + kc + 32);
            pb1 = *(const float4*)(Wb2 + kc + 32);
        }

        int ar = lane >> 2, at = lane & 3;
        #pragma unroll
        for (int kb = 0; kb < 32; kb += 8) {
            uint32_t afr[2][4], bfr[2][2];
            int ak = kb + at;
            #pragma unroll
            for (int mi = 0; mi < 2; mi++) {
                int r = wm0 + mi*16 + ar;
                afr[mi][0] = As[r  ][ak];
                afr[mi][1] = As[r+8][ak];
                afr[mi][2] = As[r  ][ak+4];
                afr[mi][3] = As[r+8][ak+4];
            }
            #pragma unroll
            for (int ni = 0; ni < 2; ni++) {
                int r = wn0 + ni*8 + ar;
                bfr[ni][0] = Bs[r][ak];
                bfr[ni][1] = Bs[r][ak+4];
            }
            #pragma unroll
            for (int mi = 0; mi < 2; mi++)
                #pragma unroll
                for (int ni = 0; ni < 2; ni++)
                    mma_tf32(acc[mi][ni],
                             afr[mi][0], afr[mi][1], afr[mi][2], afr[mi][3],
                             bfr[ni][0], bfr[ni][1]);
        }
    }
}

#define EPI_LOOP(body)                                                        \
    {                                                                         \
        int lane = threadIdx.x & 31, wrp = threadIdx.x >> 5;                  \
        int wm0 = (wrp >> 2) * 32, wn0 = (wrp & 3) * 16;                      \
        _Pragma("unroll")                                                     \
        for (int mi = 0; mi < 2; mi++) {                                      \
            _Pragma("unroll")                                                 \
            for (int ni = 0; ni < 2; ni++) {                                  \
                int rm = m0 + wm0 + mi*16 + (lane >> 2);                      \
                int cn = n0 + wn0 + ni*8 + (lane & 3)*2;                      \
                _Pragma("unroll")                                             \
                for (int hh2 = 0; hh2 < 2; hh2++) {                           \
                    int m = rm + hh2*8;                                       \
                    float v0 = acc[mi][ni][hh2*2 + 0];                        \
                    float v1 = acc[mi][ni][hh2*2 + 1];                        \
                    body                                                      \
                }                                                             \
            }                                                                 \
        }                                                                     \
    }

// ---------------- general NT GEMM ----------------
// MODE 0: C = AB     MODE 1: C = gelu(AB + bias)
template <int MODE>
__global__ __launch_bounds__(256)
void gemm_nt_tc(const float* __restrict__ A, const float* __restrict__ W,
                const float* __restrict__ bias,
                float* __restrict__ C, int N, int K)
{
    GDC();
    __shared__ __align__(16) uint32_t As[64][SM_STRIDE];
    __shared__ __align__(16) uint32_t Bs[64][SM_STRIDE];
    int m0 = blockIdx.y * 64, n0 = blockIdx.x * 64;
    float acc[2][2][4] = {};
    gemm_tc_body(A, W, K, K, 0, K, m0, n0, acc, As, Bs);

    EPI_LOOP({
        if (MODE == 1) { v0 = gelu_tanh(v0 + bias[cn]); v1 = gelu_tanh(v1 + bias[cn+1]); }
        C[(size_t)m*N + cn]     = v0;
        C[(size_t)m*N + cn + 1] = v1;
    })
}

// ---------------- fused Q/K/V projection ----------------
__global__ __launch_bounds__(256)
void gemm_qkv_tc(const float* __restrict__ A,
                 const float* __restrict__ Wq, const float* __restrict__ Wk,
                 const float* __restrict__ Wv)
{
    GDC();
    __shared__ __align__(16) uint32_t As[64][SM_STRIDE];
    __shared__ __align__(16) uint32_t Bs[64][SM_STRIDE];
    int z = blockIdx.z;
    const float* W = (z == 0) ? Wq : (z == 1) ? Wk : Wv;
    float* C = (z == 0) ? g_q : (z == 1) ? g_k : g_v;
    int m0 = blockIdx.y * 64, n0 = blockIdx.x * 64;
    float acc[2][2][4] = {};
    gemm_tc_body(A, W, DM, DM, 0, DM, m0, n0, acc, As, Bs);

    EPI_LOOP({
        C[(size_t)m*DM + cn]     = v0;
        C[(size_t)m*DM + cn + 1] = v1;
    })
}

// ---------------- split-K GEMM (N = 512): wo (K=512,split2), w2 (K=2048,split4) ----------------
__global__ __launch_bounds__(256)
void gemm_splitk_tc(const float* __restrict__ A, const float* __restrict__ W,
                    int ld, int klen)
{
    GDC();
    __shared__ __align__(16) uint32_t As[64][SM_STRIDE];
    __shared__ __align__(16) uint32_t Bs[64][SM_STRIDE];
    int z = blockIdx.z;
    int m0 = blockIdx.y * 64, n0 = blockIdx.x * 64;
    float acc[2][2][4] = {};
    gemm_tc_body(A, W, ld, ld, z*klen, klen, m0, n0, acc, As, Bs);

    float* part = g_part + (size_t)z * (BB*TT*DM);
    EPI_LOOP({
        part[(size_t)m*DM + cn]     = v0;
        part[(size_t)m*DM + cn + 1] = v1;
    })
}

// ---------------- attention: one block per (q, head, batch) ----------------
__global__ __launch_bounds__(128)
void attn_kernel() {
    GDC();
    int qi = blockIdx.x;
    int hh = blockIdx.y;
    int b  = blockIdx.z;
    int tid = threadIdx.x;
    int lane = tid & 31, wrp = tid >> 5;

    __shared__ float qs[DH];
    __shared__ float wsh[TT];
    __shared__ float redm[4];
    __shared__ float reds[4];

    const float* qrow = g_q + (size_t)(b*TT + qi)*DM + hh*DH;
    if (tid < DH) qs[tid] = qrow[tid];
    __syncthreads();

    const float* krow = g_k + (size_t)(b*TT + tid)*DM + hh*DH;
    float s = 0.0f;
    #pragma unroll 16
    for (int d = 0; d < DH; d++) s += qs[d] * krow[d];
    float lg = (tid > qi) ? s * 0.125f : NEG_INF;

    float m = lg;
    #pragma unroll
    for (int off = 16; off; off >>= 1) m = fmaxf(m, __shfl_xor_sync(0xffffffffu, m, off));
    if (lane == 0) redm[wrp] = m;
    __syncthreads();
    m = fmaxf(fmaxf(redm[0], redm[1]), fmaxf(redm[2], redm[3]));

    float e = expf(lg - m);
    wsh[tid] = e;
    float sm = e;
    #pragma unroll
    for (int off = 16; off; off >>= 1) sm += __shfl_xor_sync(0xffffffffu, sm, off);
    if (lane == 0) reds[wrp] = sm;
    __syncthreads();
    float inv = 1.0f / (reds[0] + reds[1] + reds[2] + reds[3]);

    if (tid < DH) {
        const float* vcol = g_v + (size_t)b*TT*DM + hh*DH + tid;
        float acc = 0.0f;
        #pragma unroll 8
        for (int j = 0; j < TT; j++) acc += wsh[j] * vcol[(size_t)j*DM];
        g_attn[(size_t)(b*TT + qi)*DM + hh*DH + tid] = acc * inv;
    }
}

// ---------------- layernorm (+ fused split-K reduction + residual + bias) ----------------
template <int NPART>
__global__ __launch_bounds__(256)
void ln_kernel(const float* __restrict__ X, const float* __restrict__ bias,
               const float* __restrict__ gg, const float* __restrict__ bb,
               float* __restrict__ O)
{
    GDC();
    int rrow = blockIdx.x, tid = threadIdx.x;
    const float* x = X + (size_t)rrow * DM;
    float x0 = x[tid], x1 = x[tid + 256];
    if (bias) {
        x0 += bias[tid];
        x1 += bias[tid + 256];
    }
    #pragma unroll
    for (int z = 0; z < NPART; z++) {
        const float* p = g_part + (size_t)z*(BB*TT*DM) + (size_t)rrow*DM;
        x0 += p[tid];
        x1 += p[tid + 256];
    }

    __shared__ float red[8];
    __shared__ float stats[2];
    int lane = tid & 31, warp = tid >> 5;

    float s = x0 + x1;
    for (int off = 16; off; off >>= 1) s += __shfl_down_sync(0xffffffffu, s, off);
    if (!lane) red[warp] = s;
    __syncthreads();
    if (tid == 0) {
        float t = 0; for (int i = 0; i < 8; i++) t += red[i];
        stats[0] = t * (1.0f / DM);
    }
    __syncthreads();
    float mu = stats[0];
    float d0 = x0 - mu, d1 = x1 - mu;
    s = d0*d0 + d1*d1;
    __syncthreads();
    for (int off = 16; off; off >>= 1) s += __shfl_down_sync(0xffffffffu, s, off);
    if (!lane) red[warp] = s;
    __syncthreads();
    if (tid == 0) {
        float t = 0; for (int i = 0; i < 8; i++) t += red[i];
        stats[1] = rsqrtf(t * (1.0f / DM) + 1e-5f);
    }
    __syncthreads();
    float rstd = stats[1];
    O[(size_t)rrow*DM + tid]       = d0 * rstd * gg[tid]       + bb[tid];
    O[(size_t)rrow*DM + tid + 256] = d1 * rstd * gg[tid + 256] + bb[tid + 256];
}

// ---------------- ctx-term for refine ----------------
__global__ __launch_bounds__(256)
void ctxterm_kernel(const float* __restrict__ Wr1, const float* __restrict__ br1,
                    const float* __restrict__ bemb, int step)
{
    GDC();
    int ridx = blockIdx.x * 8 + (threadIdx.x >> 5);
    int lane = threadIdx.x & 31;
    int b = ridx >> 11;
    int i = ridx & 2047;
    int ptr = THIST + step;
    const float* ctx = g_h + (size_t)(b*TT + ptr - 1)*DM;
    const float* w1  = Wr1 + (size_t)i * (2*DM);
    float s1 = 0.0f, s2 = 0.0f;
    for (int j = lane; j < DM; j += 32) {
        s1 += w1[j]      * bemb[j];
        s2 += w1[DM + j] * ctx[j];
    }
    for (int off = 16; off; off >>= 1) {
        s1 += __shfl_down_sync(0xffffffffu, s1, off);
        s2 += __shfl_down_sync(0xffffffffu, s2, off);
    }
    if (lane == 0) g_ctxterm[b*DFF + i] = s2 + SCALE_EMB * s1 + br1[i];
}

// ---------------- refine loop: one block per batch ----------------
__global__ __launch_bounds__(256)
void refine_kernel(const float* __restrict__ Wr2, const float* __restrict__ br2,
                   float* __restrict__ out, int step)
{
    GDC();
    int b = blockIdx.x;
    int tid = threadIdx.x;
    int ptr = THIST + step;

    __shared__ float cur[DIN];
    __shared__ float gact[DFF];

    if (tid < DIN) cur[tid] = g_buf[(size_t)(b*TT + ptr - 1)*DIN + tid];
    __syncthreads();

    for (int it = 0; it < NSUB; it++) {
        for (int i = tid; i < DFF; i += 256) {
            float s = g_ctxterm[b*DFF + i];
            const float* wf = g_wfused + i*DIN;
            #pragma unroll
            for (int m = 0; m < DIN; m++) s += wf[m] * cur[m];
            gact[i] = gelu_tanh(s);
        }
        __syncthreads();
        int warp = tid >> 5, lane = tid & 31;
        for (int m = warp*4; m < warp*4 + 4; m++) {
            float s = 0.0f;
            for (int i = lane; i < DFF; i += 32) s += Wr2[(size_t)m*DFF + i] * gact[i];
            for (int off = 16; off; off >>= 1) s += __shfl_down_sync(0xffffffffu, s, off);
            if (lane == 0) cur[m] += s + br2[m];
        }
        __syncthreads();
    }

    if (tid < DIN) {
        float v = cur[tid];
        g_buf[(size_t)(b*TT + ptr)*DIN + tid] = v;
        out[(size_t)(b*NSTEPS + step)*DIN + tid] = v;
    }
}

// ---------------- host: PDL launch helper ----------------
static inline void launch_pdl(const void* fn, dim3 grid, dim3 block, void** args)
{
    cudaLaunchConfig_t cfg = {};
    cfg.gridDim  = grid;
    cfg.blockDim = block;
    cfg.dynamicSmemBytes = 0;
    cfg.stream = 0;
    cudaLaunchAttribute at[1];
    at[0].id = cudaLaunchAttributeProgrammaticStreamSerialization;
    at[0].val.programmaticStreamSerializationAllowed = 1;
    cfg.attrs = at;
    cfg.numAttrs = 1;
    cudaLaunchKernelExC(&cfg, fn, args);
}

// ---------------- host orchestration ----------------
extern "C" void kernel_launch(void* const* d_in, const int* in_sizes, int n_in,
                              void* d_out, int out_size)
{
    const float* hist = (const float*)d_in[0];
    // d_in[1] = steps (int), fixed at 8
    const float* Wemb = (const float*)d_in[2];
    const float* bemb = (const float*)d_in[3];
    const float* Wq   = (const float*)d_in[4];
    const float* Wk   = (const float*)d_in[5];
    const float* Wv   = (const float*)d_in[6];
    const float* Wo   = (const float*)d_in[7];
    const float* ln1g = (const float*)d_in[8];
    const float* ln1b = (const float*)d_in[9];
    const float* W1   = (const float*)d_in[10];
    const float* b1   = (const float*)d_in[11];
    const float* W2   = (const float*)d_in[12];
    const float* b2   = (const float*)d_in[13];
    const float* ln2g = (const float*)d_in[14];
    const float* ln2b = (const float*)d_in[15];
    const float* Wr1  = (const float*)d_in[16];
    const float* br1  = (const float*)d_in[17];
    const float* Wr2  = (const float*)d_in[18];
    const float* br2  = (const float*)d_in[19];
    float* out = (float*)d_out;

    float *p_h, *p_attn, *p_ff;
    cudaGetSymbolAddress((void**)&p_h,    g_h);
    cudaGetSymbolAddress((void**)&p_attn, g_attn);
    cudaGetSymbolAddress((void**)&p_ff,   g_ff);

    const int M = BB * TT;   // 512
    int ld_dm = DM, ld_ff = DFF, k256 = 256, k512 = 512;
    int n_ff = DFF, kk = DM;

    {   void* a[] = { (void*)&hist };
        launch_pdl((const void*)init_kernel, dim3(64), dim3(256), a); }
    {   void* a[] = { (void*)&Wr1, (void*)&Wemb };
        launch_pdl((const void*)wfused_kernel, dim3(256), dim3(256), a); }

    for (int step = 0; step < NSTEPS; step++) {
        {   void* a[] = { (void*)&Wemb, (void*)&bemb };
            launch_pdl((const void*)embed_kernel, dim3(M), dim3(128), a); }

        for (int l = 0; l < NL; l++) {
            const float* wq = Wq + (size_t)l*DM*DM;
            const float* wk = Wk + (size_t)l*DM*DM;
            const float* wv = Wv + (size_t)l*DM*DM;
            const float* wo = Wo + (size_t)l*DM*DM;
            const float* w1 = W1 + (size_t)l*DFF*DM;
            const float* w2 = W2 + (size_t)l*DM*DFF;
            const float* pb1  = b1 + (size_t)l*DFF;
            const float* pb2  = b2 + (size_t)l*DM;
            const float* pl1g = ln1g + (size_t)l*DM;
            const float* pl1b = ln1b + (size_t)l*DM;
            const float* pl2g = ln2g + (size_t)l*DM;
            const float* pl2b = ln2b + (size_t)l*DM;
            const float* nullbias = nullptr;

            {   void* a[] = { (void*)&p_h, (void*)&wq, (void*)&wk, (void*)&wv };
                launch_pdl((const void*)gemm_qkv_tc, dim3(DM/64, M/64, 3), dim3(256), a); }

            launch_pdl((const void*)attn_kernel, dim3(TT, NH, BB), dim3(128), nullptr);

            {   void* a[] = { (void*)&p_attn, (void*)&wo, (void*)&ld_dm, (void*)&k256 };
                launch_pdl((const void*)gemm_splitk_tc, dim3(DM/64, M/64, 2), dim3(256), a); }

            {   void* a[] = { (void*)&p_h, (void*)&nullbias, (void*)&pl1g, (void*)&pl1b, (void*)&p_h };
                launch_pdl((const void*)ln_kernel<2>, dim3(M), dim3(256), a); }

            {   void* a[] = { (void*)&p_h, (void*)&w1, (void*)&pb1, (void*)&p_ff, (void*)&n_ff, (void*)&kk };
                launch_pdl((const void*)gemm_nt_tc<1>, dim3(DFF/64, M/64), dim3(256), a); }

            {   void* a[] = { (void*)&p_ff, (void*)&w2, (void*)&ld_ff, (void*)&k512 };
                launch_pdl((const void*)gemm_splitk_tc, dim3(DM/64, M/64, 4), dim3(256), a); }

            {   void* a[] = { (void*)&p_h, (void*)&pb2, (void*)&pl2g, (void*)&pl2b, (void*)&p_h };
                launch_pdl((const void*)ln_kernel<4>, dim3(M), dim3(256), a); }
        }

        {   void* a[] = { (void*)&Wr1, (void*)&br1, (void*)&bemb, (void*)&step };
            launch_pdl((const void*)ctxterm_kernel, dim3(1024), dim3(256), a); }
        {   void* a[] = { (void*)&Wr2, (void*)&br2, (void*)&out, (void*)&step };
            launch_pdl((const void*)refine_kernel, dim3(BB), dim3(256), a); }
    }
}

// round 11
// speedup vs baseline: 1.7438x; 1.7438x over previous
#include <cuda_runtime.h>
#include <cuda_bf16.h>
#include <cstdint>

// ---------------- problem constants ----------------
#define BB      4
#define TT      128
#define THIST   120
#define NSTEPS  8
#define DM      512
#define NH      8
#define DH      64
#define DFF     2048
#define DIN     32
#define NL      4
#define NSUB    5

#define SCALE_EMB 22.627416997969522f   // sqrt(512)
#define NEG_INF  (-3.402823466e38f)
#define LN10000  9.210340371976184f

// ---------------- device scratch (static, no allocation) ----------------
__device__ float g_buf [BB*TT*DIN];
__device__ float g_h   [BB*TT*DM];
__device__ float g_q   [BB*TT*DM];
__device__ float g_k   [BB*TT*DM];
__device__ float g_v   [BB*TT*DM];
__device__ float g_attn[BB*TT*DM];
__device__ float g_ff  [BB*TT*DFF];
__device__ float g_part[4*BB*TT*DM];    // split-K partials (wo uses 2, w2 uses 4)
__device__ float g_wfused [DFF*DIN];
__device__ float g_ctxterm[BB*DFF];

// ---------------- helpers ----------------
__device__ __forceinline__ float gelu_tanh(float x) {
    float x3 = x * x * x;
    float t  = tanhf(0.7978845608028654f * (x + 0.044715f * x3));
    return 0.5f * x * (1.0f + t);
}

__device__ __forceinline__ uint32_t f2tf32(float x) {
    uint32_t r;
    asm("cvt.rna.tf32.f32 %0, %1;" : "=r"(r) : "f"(x));
    return r;
}

__device__ __forceinline__ void mma_tf32(float c[4],
    uint32_t a0, uint32_t a1, uint32_t a2, uint32_t a3,
    uint32_t b0, uint32_t b1)
{
    asm volatile(
        "mma.sync.aligned.m16n8k8.row.col.f32.tf32.tf32.f32 "
        "{%0,%1,%2,%3}, {%4,%5,%6,%7}, {%8,%9}, {%0,%1,%2,%3};"
        : "+f"(c[0]), "+f"(c[1]), "+f"(c[2]), "+f"(c[3])
        : "r"(a0), "r"(a1), "r"(a2), "r"(a3), "r"(b0), "r"(b1));
}

// ---------------- init: buf = [history ; zeros] ----------------
__global__ void init_kernel(const float* __restrict__ hist) {
    int idx = blockIdx.x * 256 + threadIdx.x;
    if (idx >= BB*TT*DIN) return;
    int b = idx >> 12;
    int t = (idx >> 5) & 127;
    int k = idx & 31;
    g_buf[idx] = (t < THIST) ? hist[(b*THIST + t)*DIN + k] : 0.0f;
}

// ---------------- precompute Wfused = scale * Wr1[:, :512] @ W_emb ----------------
__global__ void wfused_kernel(const float* __restrict__ Wr1, const float* __restrict__ Wemb) {
    int idx = blockIdx.x * 256 + threadIdx.x;
    int i = idx >> 5;
    int m = idx & 31;
    const float* w = Wr1 + (size_t)i * (2*DM);
    float s = 0.0f;
    #pragma unroll 8
    for (int j = 0; j < DM; j++) s += w[j] * Wemb[j*DIN + m];
    g_wfused[i*DIN + m] = s * SCALE_EMB;
}

// ---------------- embedding + positional encoding ----------------
__global__ void embed_kernel(const float* __restrict__ Wemb, const float* __restrict__ bemb) {
    int bt = blockIdx.x;                 // 0..511
    int t  = bt & 127;
    __shared__ float row[DIN];
    if (threadIdx.x < DIN) row[threadIdx.x] = g_buf[bt*DIN + threadIdx.x];
    __syncthreads();
    for (int d = threadIdx.x; d < DM; d += blockDim.x) {
        float s = bemb[d];
        const float* w = Wemb + d*DIN;
        #pragma unroll
        for (int k = 0; k < DIN; k++) s += row[k] * w[k];
        int i = d >> 1;
        float div = expf((float)(2*i) * (-LN10000 / (float)DM));
        float ang = (float)t * div;
        float pe  = (d & 1) ? cosf(ang) : sinf(ang);
        g_h[bt*DM + d] = s * SCALE_EMB + pe;
    }
}

// ================= tf32 tensor-core tile body (256 threads) =================
// tile 64x64, K chunk 32; 8 warps 2x4, warp does 32x16. Smem stride 36.
#define SM_STRIDE 36

__device__ __forceinline__ void gemm_tc_body(
    const float* __restrict__ A, const float* __restrict__ W,
    int lda, int ldw, int kbeg, int klen,
    int m0, int n0, float acc[2][2][4],
    uint32_t (*As)[SM_STRIDE], uint32_t (*Bs)[SM_STRIDE])
{
    int tid  = threadIdx.x;
    int lane = tid & 31;
    int wrp  = tid >> 5;
    int wm0 = (wrp >> 2) * 32;
    int wn0 = (wrp & 3) * 16;

    int lrow = tid >> 3;          // 0..31
    int lcol = (tid & 7) * 4;     // 0..28

    const float* Ab  = A + (size_t)(m0 + lrow) * lda + kbeg + lcol;
    const float* Ab2 = Ab + (size_t)32 * lda;
    const float* Wb  = W + (size_t)(n0 + lrow) * ldw + kbeg + lcol;
    const float* Wb2 = Wb + (size_t)32 * ldw;

    float4 pa0 = *(const float4*)(Ab);
    float4 pa1 = *(const float4*)(Ab2);
    float4 pb0 = *(const float4*)(Wb);
    float4 pb1 = *(const float4*)(Wb2);

    for (int kc = 0; kc < klen; kc += 32) {
        __syncthreads();
        {
            uint4 u;
            u.x=f2tf32(pa0.x); u.y=f2tf32(pa0.y); u.z=f2tf32(pa0.z); u.w=f2tf32(pa0.w);
            *(uint4*)&As[lrow][lcol] = u;
            u.x=f2tf32(pa1.x); u.y=f2tf32(pa1.y); u.z=f2tf32(pa1.z); u.w=f2tf32(pa1.w);
            *(uint4*)&As[lrow+32][lcol] = u;
            u.x=f2tf32(pb0.x); u.y=f2tf32(pb0.y); u.z=f2tf32(pb0.z); u.w=f2tf32(pb0.w);
            *(uint4*)&Bs[lrow][lcol] = u;
            u.x=f2tf32(pb1.x); u.y=f2tf32(pb1.y); u.z=f2tf32(pb1.z); u.w=f2tf32(pb1.w);
            *(uint4*)&Bs[lrow+32][lcol] = u;
        }
        __syncthreads();

        if (kc + 32 < klen) {
            pa0 = *(const float4*)(Ab  + kc + 32);
            pa1 = *(const float4*)(Ab2 + kc + 32);
            pb0 = *(const float4*)(Wb  + kc + 32);
            pb1 = *(const float4*)(Wb2 + kc + 32);
        }

        int ar = lane >> 2, at = lane & 3;
        #pragma unroll
        for (int kb = 0; kb < 32; kb += 8) {
            uint32_t afr[2][4], bfr[2][2];
            int ak = kb + at;
            #pragma unroll
            for (int mi = 0; mi < 2; mi++) {
                int r = wm0 + mi*16 + ar;
                afr[mi][0] = As[r  ][ak];
                afr[mi][1] = As[r+8][ak];
                afr[mi][2] = As[r  ][ak+4];
                afr[mi][3] = As[r+8][ak+4];
            }
            #pragma unroll
            for (int ni = 0; ni < 2; ni++) {
                int r = wn0 + ni*8 + ar;
                bfr[ni][0] = Bs[r][ak];
                bfr[ni][1] = Bs[r][ak+4];
            }
            #pragma unroll
            for (int mi = 0; mi < 2; mi++)
                #pragma unroll
                for (int ni = 0; ni < 2; ni++)
                    mma_tf32(acc[mi][ni],
                             afr[mi][0], afr[mi][1], afr[mi][2], afr[mi][3],
                             bfr[ni][0], bfr[ni][1]);
        }
    }
}

#define EPI_LOOP(body)                                                        \
    {                                                                         \
        int lane = threadIdx.x & 31, wrp = threadIdx.x >> 5;                  \
        int wm0 = (wrp >> 2) * 32, wn0 = (wrp & 3) * 16;                      \
        _Pragma("unroll")                                                     \
        for (int mi = 0; mi < 2; mi++) {                                      \
            _Pragma("unroll")                                                 \
            for (int ni = 0; ni < 2; ni++) {                                  \
                int rm = m0 + wm0 + mi*16 + (lane >> 2);                      \
                int cn = n0 + wn0 + ni*8 + (lane & 3)*2;                      \
                _Pragma("unroll")                                             \
                for (int hh2 = 0; hh2 < 2; hh2++) {                           \
                    int m = rm + hh2*8;                                       \
                    float v0 = acc[mi][ni][hh2*2 + 0];                        \
                    float v1 = acc[mi][ni][hh2*2 + 1];                        \
                    body                                                      \
                }                                                             \
            }                                                                 \
        }                                                                     \
    }

// ---------------- general NT GEMM ----------------
// MODE 0: C = AB     MODE 1: C = gelu(AB + bias)
template <int MODE>
__global__ __launch_bounds__(256)
void gemm_nt_tc(const float* __restrict__ A, const float* __restrict__ W,
                const float* __restrict__ bias,
                float* __restrict__ C, int N, int K)
{
    __shared__ __align__(16) uint32_t As[64][SM_STRIDE];
    __shared__ __align__(16) uint32_t Bs[64][SM_STRIDE];
    int m0 = blockIdx.y * 64, n0 = blockIdx.x * 64;
    float acc[2][2][4] = {};
    gemm_tc_body(A, W, K, K, 0, K, m0, n0, acc, As, Bs);

    EPI_LOOP({
        if (MODE == 1) { v0 = gelu_tanh(v0 + bias[cn]); v1 = gelu_tanh(v1 + bias[cn+1]); }
        C[(size_t)m*N + cn]     = v0;
        C[(size_t)m*N + cn + 1] = v1;
    })
}

// ---------------- fused Q/K/V projection ----------------
__global__ __launch_bounds__(256)
void gemm_qkv_tc(const float* __restrict__ A,
                 const float* __restrict__ Wq, const float* __restrict__ Wk,
                 const float* __restrict__ Wv)
{
    __shared__ __align__(16) uint32_t As[64][SM_STRIDE];
    __shared__ __align__(16) uint32_t Bs[64][SM_STRIDE];
    int z = blockIdx.z;
    const float* W = (z == 0) ? Wq : (z == 1) ? Wk : Wv;
    float* C = (z == 0) ? g_q : (z == 1) ? g_k : g_v;
    int m0 = blockIdx.y * 64, n0 = blockIdx.x * 64;
    float acc[2][2][4] = {};
    gemm_tc_body(A, W, DM, DM, 0, DM, m0, n0, acc, As, Bs);

    EPI_LOOP({
        C[(size_t)m*DM + cn]     = v0;
        C[(size_t)m*DM + cn + 1] = v1;
    })
}

// ---------------- split-K GEMM (N = 512): wo (K=512,split2), w2 (K=2048,split4) ----------------
__global__ __launch_bounds__(256)
void gemm_splitk_tc(const float* __restrict__ A, const float* __restrict__ W,
                    int ld, int klen)
{
    __shared__ __align__(16) uint32_t As[64][SM_STRIDE];
    __shared__ __align__(16) uint32_t Bs[64][SM_STRIDE];
    int z = blockIdx.z;
    int m0 = blockIdx.y * 64, n0 = blockIdx.x * 64;
    float acc[2][2][4] = {};
    gemm_tc_body(A, W, ld, ld, z*klen, klen, m0, n0, acc, As, Bs);

    float* part = g_part + (size_t)z * (BB*TT*DM);
    EPI_LOOP({
        part[(size_t)m*DM + cn]     = v0;
        part[(size_t)m*DM + cn + 1] = v1;
    })
}

// ---------------- flash-style attention: one block per (head, batch) ----------------
// 128 threads, one q per thread. K/V streamed via smem in 16-key chunks with
// online softmax. finfo.min masking semantics preserved exactly:
//  - all-masked chunk: m stays NEG_INF, weights exp(0)=1 accumulate;
//  - first real chunk rescales by exp(NEG_INF - m_real) = 0, discarding them;
//  - q=127 (all keys masked): stays uniform 1/128 like the reference.
__global__ __launch_bounds__(128)
void attn_flash() {
    int hh = blockIdx.x;   // 0..7
    int b  = blockIdx.y;   // 0..3
    int q  = threadIdx.x;  // 0..127

    __shared__ float Kc[16][68];
    __shared__ float Vc[16][68];

    float qv[DH];
    const float* qrow = g_q + (size_t)(b*TT + q)*DM + hh*DH;
    #pragma unroll
    for (int d = 0; d < DH; d++) qv[d] = qrow[d];

    float o[DH];
    #pragma unroll
    for (int d = 0; d < DH; d++) o[d] = 0.0f;
    float mo = NEG_INF, l = 0.0f;

    for (int base = 0; base < TT; base += 16) {
        __syncthreads();   // previous chunk fully consumed
        for (int idx = threadIdx.x; idx < 16*16; idx += 128) {
            int r  = idx >> 4;
            int c4 = (idx & 15) * 4;
            const float* kp = g_k + (size_t)(b*TT + base + r)*DM + hh*DH + c4;
            const float* vp = g_v + (size_t)(b*TT + base + r)*DM + hh*DH + c4;
            float4 k4 = *(const float4*)kp;
            float4 v4 = *(const float4*)vp;
            Kc[r][c4+0]=k4.x; Kc[r][c4+1]=k4.y; Kc[r][c4+2]=k4.z; Kc[r][c4+3]=k4.w;
            Vc[r][c4+0]=v4.x; Vc[r][c4+1]=v4.y; Vc[r][c4+2]=v4.z; Vc[r][c4+3]=v4.w;
        }
        __syncthreads();

        float lg[16];
        #pragma unroll
        for (int j = 0; j < 16; j++) {
            float s = 0.0f;
            #pragma unroll
            for (int d = 0; d < DH; d++) s += qv[d] * Kc[j][d];   // broadcast reads
            lg[j] = ((base + j) > q) ? s * 0.125f : NEG_INF;
        }
        float mc = lg[0];
        #pragma unroll
        for (int j = 1; j < 16; j++) mc = fmaxf(mc, lg[j]);
        float mn = fmaxf(mo, mc);
        float scale = expf(mo - mn);
        float e[16];
        float ls = 0.0f;
        #pragma unroll
        for (int j = 0; j < 16; j++) { e[j] = expf(lg[j] - mn); ls += e[j]; }
        l = l * scale + ls;
        #pragma unroll
        for (int d = 0; d < DH; d++) {
            float acc = 0.0f;
            #pragma unroll
            for (int j = 0; j < 16; j++) acc += e[j] * Vc[j][d];
            o[d] = o[d] * scale + acc;
        }
        mo = mn;
    }

    float inv = 1.0f / l;
    float* orow = g_attn + (size_t)(b*TT + q)*DM + hh*DH;
    #pragma unroll
    for (int d = 0; d < DH; d++) orow[d] = o[d] * inv;
}

// ---------------- layernorm (+ fused split-K reduction + residual + bias) ----------------
template <int NPART>
__global__ __launch_bounds__(256)
void ln_kernel(const float* __restrict__ X, const float* __restrict__ bias,
               const float* __restrict__ gg, const float* __restrict__ bb,
               float* __restrict__ O)
{
    int rrow = blockIdx.x, tid = threadIdx.x;
    const float* x = X + (size_t)rrow * DM;
    float x0 = x[tid], x1 = x[tid + 256];
    if (bias) {
        x0 += bias[tid];
        x1 += bias[tid + 256];
    }
    #pragma unroll
    for (int z = 0; z < NPART; z++) {
        const float* p = g_part + (size_t)z*(BB*TT*DM) + (size_t)rrow*DM;
        x0 += p[tid];
        x1 += p[tid + 256];
    }

    __shared__ float red[8];
    __shared__ float stats[2];
    int lane = tid & 31, warp = tid >> 5;

    float s = x0 + x1;
    for (int off = 16; off; off >>= 1) s += __shfl_down_sync(0xffffffffu, s, off);
    if (!lane) red[warp] = s;
    __syncthreads();
    if (tid == 0) {
        float t = 0; for (int i = 0; i < 8; i++) t += red[i];
        stats[0] = t * (1.0f / DM);
    }
    __syncthreads();
    float mu = stats[0];
    float d0 = x0 - mu, d1 = x1 - mu;
    s = d0*d0 + d1*d1;
    __syncthreads();
    for (int off = 16; off; off >>= 1) s += __shfl_down_sync(0xffffffffu, s, off);
    if (!lane) red[warp] = s;
    __syncthreads();
    if (tid == 0) {
        float t = 0; for (int i = 0; i < 8; i++) t += red[i];
        stats[1] = rsqrtf(t * (1.0f / DM) + 1e-5f);
    }
    __syncthreads();
    float rstd = stats[1];
    O[(size_t)rrow*DM + tid]       = d0 * rstd * gg[tid]       + bb[tid];
    O[(size_t)rrow*DM + tid + 256] = d1 * rstd * gg[tid + 256] + bb[tid + 256];
}

// ---------------- ctx-term for refine ----------------
__global__ __launch_bounds__(256)
void ctxterm_kernel(const float* __restrict__ Wr1, const float* __restrict__ br1,
                    const float* __restrict__ bemb, int step)
{
    int ridx = blockIdx.x * 8 + (threadIdx.x >> 5);
    int lane = threadIdx.x & 31;
    int b = ridx >> 11;
    int i = ridx & 2047;
    int ptr = THIST + step;
    const float* ctx = g_h + (size_t)(b*TT + ptr - 1)*DM;
    const float* w1  = Wr1 + (size_t)i * (2*DM);
    float s1 = 0.0f, s2 = 0.0f;
    for (int j = lane; j < DM; j += 32) {
        s1 += w1[j]      * bemb[j];
        s2 += w1[DM + j] * ctx[j];
    }
    for (int off = 16; off; off >>= 1) {
        s1 += __shfl_down_sync(0xffffffffu, s1, off);
        s2 += __shfl_down_sync(0xffffffffu, s2, off);
    }
    if (lane == 0) g_ctxterm[b*DFF + i] = s2 + SCALE_EMB * s1 + br1[i];
}

// ---------------- refine loop: one block per batch ----------------
__global__ __launch_bounds__(256)
void refine_kernel(const float* __restrict__ Wr2, const float* __restrict__ br2,
                   float* __restrict__ out, int step)
{
    int b = blockIdx.x;
    int tid = threadIdx.x;
    int ptr = THIST + step;

    __shared__ float cur[DIN];
    __shared__ float gact[DFF];

    if (tid < DIN) cur[tid] = g_buf[(size_t)(b*TT + ptr - 1)*DIN + tid];
    __syncthreads();

    for (int it = 0; it < NSUB; it++) {
        for (int i = tid; i < DFF; i += 256) {
            float s = g_ctxterm[b*DFF + i];
            const float* wf = g_wfused + i*DIN;
            #pragma unroll
            for (int m = 0; m < DIN; m++) s += wf[m] * cur[m];
            gact[i] = gelu_tanh(s);
        }
        __syncthreads();
        int warp = tid >> 5, lane = tid & 31;
        for (int m = warp*4; m < warp*4 + 4; m++) {
            float s = 0.0f;
            for (int i = lane; i < DFF; i += 32) s += Wr2[(size_t)m*DFF + i] * gact[i];
            for (int off = 16; off; off >>= 1) s += __shfl_down_sync(0xffffffffu, s, off);
            if (lane == 0) cur[m] += s + br2[m];
        }
        __syncthreads();
    }

    if (tid < DIN) {
        float v = cur[tid];
        g_buf[(size_t)(b*TT + ptr)*DIN + tid] = v;
        out[(size_t)(b*NSTEPS + step)*DIN + tid] = v;
    }
}

// ---------------- host orchestration ----------------
extern "C" void kernel_launch(void* const* d_in, const int* in_sizes, int n_in,
                              void* d_out, int out_size)
{
    const float* hist = (const float*)d_in[0];
    // d_in[1] = steps (int), fixed at 8
    const float* Wemb = (const float*)d_in[2];
    const float* bemb = (const float*)d_in[3];
    const float* Wq   = (const float*)d_in[4];
    const float* Wk   = (const float*)d_in[5];
    const float* Wv   = (const float*)d_in[6];
    const float* Wo   = (const float*)d_in[7];
    const float* ln1g = (const float*)d_in[8];
    const float* ln1b = (const float*)d_in[9];
    const float* W1   = (const float*)d_in[10];
    const float* b1   = (const float*)d_in[11];
    const float* W2   = (const float*)d_in[12];
    const float* b2   = (const float*)d_in[13];
    const float* ln2g = (const float*)d_in[14];
    const float* ln2b = (const float*)d_in[15];
    const float* Wr1  = (const float*)d_in[16];
    const float* br1  = (const float*)d_in[17];
    const float* Wr2  = (const float*)d_in[18];
    const float* br2  = (const float*)d_in[19];
    float* out = (float*)d_out;

    float *p_h, *p_attn, *p_ff;
    cudaGetSymbolAddress((void**)&p_h,    g_h);
    cudaGetSymbolAddress((void**)&p_attn, g_attn);
    cudaGetSymbolAddress((void**)&p_ff,   g_ff);

    const int M = BB * TT;   // 512

    init_kernel<<<64, 256>>>(hist);
    wfused_kernel<<<256, 256>>>(Wr1, Wemb);

    for (int step = 0; step < NSTEPS; step++) {
        embed_kernel<<<M, 128>>>(Wemb, bemb);

        for (int l = 0; l < NL; l++) {
            const float* wq = Wq + (size_t)l*DM*DM;
            const float* wk = Wk + (size_t)l*DM*DM;
            const float* wv = Wv + (size_t)l*DM*DM;
            const float* wo = Wo + (size_t)l*DM*DM;
            const float* w1 = W1 + (size_t)l*DFF*DM;
            const float* w2 = W2 + (size_t)l*DM*DFF;

            dim3 gqkv(DM/64, M/64, 3);  // 192 CTAs
            dim3 gff (DFF/64, M/64);    // 256 CTAs
            dim3 gwo (DM/64, M/64, 2);  // split-K=2: 128 CTAs
            dim3 gw2 (DM/64, M/64, 4);  // split-K=4: 256 CTAs

            gemm_qkv_tc<<<gqkv, 256>>>(p_h, wq, wk, wv);
            attn_flash<<<dim3(NH, BB), 128>>>();

            gemm_splitk_tc<<<gwo, 256>>>(p_attn, wo, DM, 256);
            ln_kernel<2><<<M, 256>>>(p_h, nullptr, ln1g + l*DM, ln1b + l*DM, p_h);

            gemm_nt_tc<1><<<gff, 256>>>(p_h, w1, b1 + l*DFF, p_ff, DFF, DM);
            gemm_splitk_tc<<<gw2, 256>>>(p_ff, w2, DFF, 512);
            ln_kernel<4><<<M, 256>>>(p_h, b2 + l*DM, ln2g + l*DM, ln2b + l*DM, p_h);
        }

        ctxterm_kernel<<<1024, 256>>>(Wr1, br1, bemb, step);
        refine_kernel<<<BB, 256>>>(Wr2, br2, out, step);
    }
}